// round 17
// baseline (speedup 1.0000x reference)
#include <cuda_runtime.h>
#include <cuda_bf16.h>
#include <cstdint>

// Problem dims (fixed by the dataset)
#define BROWS 8192
#define DDIM  784
#define HDIM  500
#define CDIM  512
#define SDIM  16
#define CSDIM (CDIM * SDIM)      // 8192
#define NROWS2 (BROWS * SDIM)    // 131072
#define BK 16
#define VQ_BAND 1e-4f

// -------- scratch (no allocations allowed) ----
__device__ float g_h1[BROWS * HDIM];
__device__ float g_h2[BROWS * HDIM];
__device__ float g_cnorm[CDIM];
__device__ int   g_codes[NROWS2];
__device__ float g_table[SDIM * CDIM * 512];               // 16.8 MB
__device__ __nv_bfloat16 g_obs_hi[(size_t)NROWS2 * CDIM];  // 134 MB
__device__ __nv_bfloat16 g_obs_lo[(size_t)NROWS2 * CDIM];  // 134 MB
__device__ __nv_bfloat16 g_cb_hi[CDIM * CDIM];
__device__ __nv_bfloat16 g_cb_lo[CDIM * CDIM];
__device__ __nv_bfloat16 g_h2h[BROWS * CDIM];              // h2 split, K padded 500->512
__device__ __nv_bfloat16 g_h2l[BROWS * CDIM];
__device__ __nv_bfloat16 g_w3th[(size_t)CSDIM * CDIM];     // W3^T split [n][k]
__device__ __nv_bfloat16 g_w3tl[(size_t)CSDIM * CDIM];
__device__ int g_amb_rows[NROWS2];
__device__ int g_amb_count;

// ---------------- packed f32x2 helpers ----------------
__device__ __forceinline__ uint64_t pack_dup(float x) {
    uint64_t r;
    asm("mov.b64 %0, {%1, %1};" : "=l"(r) : "f"(x));
    return r;
}
__device__ __forceinline__ void ffma2(uint64_t& d, uint64_t a, uint64_t b) {
    asm("fma.rn.f32x2 %0, %1, %2, %0;" : "+l"(d) : "l"(a), "l"(b));
}
__device__ __forceinline__ float2 unpack2(uint64_t v) {
    float lo, hi;
    asm("mov.b64 {%0, %1}, %2;" : "=f"(lo), "=f"(hi) : "l"(v));
    return make_float2(lo, hi);
}

// ---------------- bf16 mma helper (m16n8k16, row.col, f32 acc) ----------------
__device__ __forceinline__ void mma_bf16(float* d, const uint32_t* a,
                                         uint32_t b0, uint32_t b1) {
    asm volatile(
        "mma.sync.aligned.m16n8k16.row.col.f32.bf16.bf16.f32 "
        "{%0,%1,%2,%3}, {%4,%5,%6,%7}, {%8,%9}, {%0,%1,%2,%3};"
        : "+f"(d[0]), "+f"(d[1]), "+f"(d[2]), "+f"(d[3])
        : "r"(a[0]), "r"(a[1]), "r"(a[2]), "r"(a[3]), "r"(b0), "r"(b1));
}

// ============================================================================
// Codebook row norms in DOUBLE (one warp per row)
// ============================================================================
__global__ void cnorm_kernel(const float* __restrict__ cb, float* __restrict__ cn) {
    int warp = (blockIdx.x * blockDim.x + threadIdx.x) >> 5;
    int lane = threadIdx.x & 31;
    if (warp >= CDIM) return;
    const float* row = cb + (size_t)warp * CDIM;
    double s = 0.0;
    for (int k = lane; k < CDIM; k += 32) { double v = (double)row[k]; s += v * v; }
    #pragma unroll
    for (int o = 16; o > 0; o >>= 1) s += __shfl_down_sync(0xffffffffu, s, o);
    if (lane == 0) cn[warp] = (float)s;
}

// ============================================================================
// fp32 -> split bf16 (hi + lo), no padding (codebook)
// ============================================================================
__global__ void convert_split(const float* __restrict__ src,
                              __nv_bfloat16* __restrict__ hi,
                              __nv_bfloat16* __restrict__ lo, int n8)
{
    int i = blockIdx.x * blockDim.x + threadIdx.x;
    if (i >= n8) return;
    const float4* s = (const float4*)src + (size_t)i * 2;
    float4 v0 = s[0], v1 = s[1];
    float v[8] = {v0.x, v0.y, v0.z, v0.w, v1.x, v1.y, v1.z, v1.w};
    __nv_bfloat16 h[8], l[8];
    #pragma unroll
    for (int e = 0; e < 8; e++) {
        h[e] = __float2bfloat16_rn(v[e]);
        l[e] = __float2bfloat16_rn(v[e] - __bfloat162float(h[e]));
    }
    uint4 oh, ol;
    oh.x = *(uint32_t*)&h[0]; oh.y = *(uint32_t*)&h[2];
    oh.z = *(uint32_t*)&h[4]; oh.w = *(uint32_t*)&h[6];
    ol.x = *(uint32_t*)&l[0]; ol.y = *(uint32_t*)&l[2];
    ol.z = *(uint32_t*)&l[4]; ol.w = *(uint32_t*)&l[6];
    ((uint4*)hi)[i] = oh;
    ((uint4*)lo)[i] = ol;
}

// ============================================================================
// h2 [8192 x 500] -> split bf16 [8192 x 512] (zero-padded cols 500..511)
// ============================================================================
__global__ void h2_split(const float* __restrict__ h2,
                         __nv_bfloat16* __restrict__ hh,
                         __nv_bfloat16* __restrict__ hl)
{
    int i = blockIdx.x * blockDim.x + threadIdx.x;   // over 8192*128
    if (i >= BROWS * 128) return;
    int b = i >> 7;
    int c0 = (i & 127) * 4;
    __nv_bfloat16 h[4], l[4];
    #pragma unroll
    for (int e = 0; e < 4; e++) {
        int c = c0 + e;
        float v = (c < HDIM) ? h2[(size_t)b * HDIM + c] : 0.f;
        h[e] = __float2bfloat16_rn(v);
        l[e] = __float2bfloat16_rn(v - __bfloat162float(h[e]));
    }
    uint2 oh, ol;
    oh.x = *(uint32_t*)&h[0]; oh.y = *(uint32_t*)&h[2];
    ol.x = *(uint32_t*)&l[0]; ol.y = *(uint32_t*)&l[2];
    *(uint2*)(hh + (size_t)b * CDIM + c0) = oh;
    *(uint2*)(hl + (size_t)b * CDIM + c0) = ol;
}

// ============================================================================
// W3 [500 x 8192] -> transposed split bf16 [8192 x 512] (k padded 500->512)
// ============================================================================
__global__ void w3t_split(const float* __restrict__ w3,
                          __nv_bfloat16* __restrict__ th,
                          __nv_bfloat16* __restrict__ tl)
{
    __shared__ float tile[32][33];
    int n0 = blockIdx.x * 32;
    int k0 = blockIdx.y * 32;
    int tx = threadIdx.x & 31;
    int ty = threadIdx.x >> 5;     // 0..7
    #pragma unroll
    for (int r = 0; r < 32; r += 8) {
        int k = k0 + ty + r;
        tile[ty + r][tx] = (k < HDIM) ? w3[(size_t)k * CSDIM + n0 + tx] : 0.f;
    }
    __syncthreads();
    #pragma unroll
    for (int r = 0; r < 32; r += 8) {
        int n = n0 + ty + r;
        int k = k0 + tx;
        float v = tile[tx][ty + r];
        __nv_bfloat16 h = __float2bfloat16_rn(v);
        __nv_bfloat16 l = __float2bfloat16_rn(v - __bfloat162float(h));
        th[(size_t)n * CDIM + k] = h;
        tl[(size_t)n * CDIM + k] = l;
    }
}

// ============================================================================
// SMALL fp32 GEMM: 128x128 block, 8x8/thread, FFMA2. (enc1/enc2/dec2)
// NUMERICS: single fp32 accumulator, ascending-k FFMA (bitwise ref-matching).
// ============================================================================
template<int RELU, int HAS_BIAS>
__global__ __launch_bounds__(256, 2)
void gemm_small(const float* __restrict__ A, const float* __restrict__ Bm,
                const float* __restrict__ bias, float* __restrict__ C,
                int N, int K, int ldc)
{
    __shared__ float As[BK][132];
    __shared__ float Bs[BK][128];

    int tid = threadIdx.x;
    int tr = tid >> 4;
    int tc = tid & 15;
    int row0 = blockIdx.y * 128;
    int col0 = blockIdx.x * 128;

    uint64_t acc2[4][8];
    #pragma unroll
    for (int p = 0; p < 4; p++)
        #pragma unroll
        for (int j = 0; j < 8; j++) acc2[p][j] = 0ull;

    for (int k0 = 0; k0 < K; k0 += BK) {
        #pragma unroll
        for (int e = 0; e < 8; e++) {
            int l = tid + e * 256;
            int m = l >> 4;
            int k = l & 15;
            int gk = k0 + k;
            float v = 0.f;
            if (gk < K) v = A[(size_t)(row0 + m) * K + gk];
            As[k][m] = v;
        }
        #pragma unroll
        for (int e = 0; e < 8; e++) {
            int l = tid + e * 256;
            int k = l >> 7;
            int n = l & 127;
            int gk = k0 + k, gn = col0 + n;
            float v = 0.f;
            if (gk < K && gn < N) v = Bm[(size_t)gk * N + gn];
            Bs[k][n] = v;
        }
        __syncthreads();

        #pragma unroll
        for (int kk = 0; kk < BK; kk++) {
            ulonglong2 va0 = *(const ulonglong2*)(&As[kk][tr * 8]);
            ulonglong2 va1 = *(const ulonglong2*)(&As[kk][tr * 8 + 4]);
            uint64_t ap[4] = {va0.x, va0.y, va1.x, va1.y};
            float4 b0 = *(const float4*)(&Bs[kk][tc * 8]);
            float4 b1 = *(const float4*)(&Bs[kk][tc * 8 + 4]);
            uint64_t bd[8];
            bd[0] = pack_dup(b0.x); bd[1] = pack_dup(b0.y);
            bd[2] = pack_dup(b0.z); bd[3] = pack_dup(b0.w);
            bd[4] = pack_dup(b1.x); bd[5] = pack_dup(b1.y);
            bd[6] = pack_dup(b1.z); bd[7] = pack_dup(b1.w);
            #pragma unroll
            for (int p = 0; p < 4; p++)
                #pragma unroll
                for (int j = 0; j < 8; j++)
                    ffma2(acc2[p][j], ap[p], bd[j]);
        }
        __syncthreads();
    }

    #pragma unroll
    for (int p = 0; p < 4; p++) {
        #pragma unroll
        for (int half = 0; half < 2; half++) {
            int r = row0 + tr * 8 + p * 2 + half;
            #pragma unroll
            for (int j = 0; j < 8; j++) {
                int c = col0 + tc * 8 + j;
                if (c < N) {
                    float2 u = unpack2(acc2[p][j]);
                    float v = half ? u.y : u.x;
                    if (HAS_BIAS) v = __fadd_rn(v, bias[c]);
                    if (RELU) v = fmaxf(v, 0.f);
                    C[(size_t)r * ldc + c] = v;
                }
            }
        }
    }
}

// ============================================================================
// Decoder table: T[s][c][n] = sum_k cb[c][k] * dec_w1[(s*512+k)*500 + n]
// ============================================================================
__global__ __launch_bounds__(256, 2)
void table_gemm(const float* __restrict__ cb, const float* __restrict__ dw1,
                float* __restrict__ table)
{
    const float* A = cb;
    const float* Bm = dw1 + (size_t)blockIdx.z * CDIM * HDIM;
    float* C = table + (size_t)blockIdx.z * CDIM * 512;

    __shared__ float As[BK][132];
    __shared__ float Bs[BK][128];

    int tid = threadIdx.x;
    int tr = tid >> 4;
    int tc = tid & 15;
    int row0 = blockIdx.y * 128;
    int col0 = blockIdx.x * 128;

    uint64_t acc2[4][8];
    #pragma unroll
    for (int p = 0; p < 4; p++)
        #pragma unroll
        for (int j = 0; j < 8; j++) acc2[p][j] = 0ull;

    for (int k0 = 0; k0 < CDIM; k0 += BK) {
        #pragma unroll
        for (int e = 0; e < 8; e++) {
            int l = tid + e * 256;
            int m = l >> 4;
            int k = l & 15;
            As[k][m] = A[(size_t)(row0 + m) * CDIM + k0 + k];
        }
        #pragma unroll
        for (int e = 0; e < 8; e++) {
            int l = tid + e * 256;
            int k = l >> 7;
            int n = l & 127;
            int gn = col0 + n;
            Bs[k][n] = (gn < HDIM) ? Bm[(size_t)(k0 + k) * HDIM + gn] : 0.f;
        }
        __syncthreads();

        #pragma unroll
        for (int kk = 0; kk < BK; kk++) {
            ulonglong2 va0 = *(const ulonglong2*)(&As[kk][tr * 8]);
            ulonglong2 va1 = *(const ulonglong2*)(&As[kk][tr * 8 + 4]);
            uint64_t ap[4] = {va0.x, va0.y, va1.x, va1.y};
            float4 b0 = *(const float4*)(&Bs[kk][tc * 8]);
            float4 b1 = *(const float4*)(&Bs[kk][tc * 8 + 4]);
            uint64_t bd[8];
            bd[0] = pack_dup(b0.x); bd[1] = pack_dup(b0.y);
            bd[2] = pack_dup(b0.z); bd[3] = pack_dup(b0.w);
            bd[4] = pack_dup(b1.x); bd[5] = pack_dup(b1.y);
            bd[6] = pack_dup(b1.z); bd[7] = pack_dup(b1.w);
            #pragma unroll
            for (int p = 0; p < 4; p++)
                #pragma unroll
                for (int j = 0; j < 8; j++)
                    ffma2(acc2[p][j], ap[p], bd[j]);
        }
        __syncthreads();
    }

    #pragma unroll
    for (int p = 0; p < 4; p++) {
        #pragma unroll
        for (int half = 0; half < 2; half++) {
            int r = row0 + tr * 8 + p * 2 + half;
            #pragma unroll
            for (int j = 0; j < 8; j++) {
                int c = col0 + tc * 8 + j;
                if (c < HDIM) {
                    float2 u = unpack2(acc2[p][j]);
                    C[(size_t)r * 512 + c] = half ? u.y : u.x;
                }
            }
        }
    }
}

// ============================================================================
// dec1 via table gather-sum
// ============================================================================
__global__ __launch_bounds__(256, 8)
void dec1_gather(const int* __restrict__ codes, const float* __restrict__ table,
                 const float* __restrict__ db1, float* __restrict__ h1)
{
    int b = blockIdx.x * 2 + (threadIdx.x >> 7);
    int t = threadIdx.x & 127;

    __shared__ int cds[2][16];
    if ((threadIdx.x & 127) < 16)
        cds[threadIdx.x >> 7][threadIdx.x & 127] = codes[b * 16 + (threadIdx.x & 127)];
    __syncthreads();

    if (t >= 125) return;
    const int* cd = cds[threadIdx.x >> 7];

    float4 acc = *(const float4*)(db1 + t * 4);
    #pragma unroll
    for (int s = 0; s < 16; s++) {
        const float4* row = (const float4*)(table + (((size_t)s * CDIM + cd[s]) << 9));
        float4 v = row[t];
        acc.x += v.x; acc.y += v.y; acc.z += v.z; acc.w += v.w;
    }
    acc.x = fmaxf(acc.x, 0.f); acc.y = fmaxf(acc.y, 0.f);
    acc.z = fmaxf(acc.z, 0.f); acc.w = fmaxf(acc.w, 0.f);
    *(float4*)(h1 + (size_t)b * HDIM + t * 4) = acc;
}

// ============================================================================
// SPLIT-bf16 3-term mma GEMM (validated): C = A.B^T + bias, 128x128 tile,
// K=512. Used for enc3 (writes fp32 obs + split bf16 obs).
// ============================================================================
#define S_LD 40

template<int WRITE_SPLIT, int HAS_BIAS>
__global__ __launch_bounds__(256)
void mma3_gemm(const __nv_bfloat16* __restrict__ ah,
               const __nv_bfloat16* __restrict__ al,
               const __nv_bfloat16* __restrict__ bh,
               const __nv_bfloat16* __restrict__ bl,
               const float* __restrict__ bias,
               float* __restrict__ out, int ldo,
               __nv_bfloat16* __restrict__ out_hi,
               __nv_bfloat16* __restrict__ out_lo)
{
    __shared__ __nv_bfloat16 Ah[128 * S_LD];
    __shared__ __nv_bfloat16 Al[128 * S_LD];
    __shared__ __nv_bfloat16 Bh[128 * S_LD];
    __shared__ __nv_bfloat16 Bl[128 * S_LD];

    int tid  = threadIdx.x;
    int lane = tid & 31;
    int wid  = tid >> 5;
    int g    = lane >> 2;
    int tg   = lane & 3;
    int wm   = (wid >> 1) * 32;
    int wn   = (wid & 1) * 64;
    int row0 = blockIdx.y * 128;
    int col0 = blockIdx.x * 128;

    int lrow  = tid >> 1;
    int lhalf = (tid & 1) * 16;
    const uint4* gAh = (const uint4*)(ah + (size_t)(row0 + lrow) * CDIM + lhalf);
    const uint4* gAl = (const uint4*)(al + (size_t)(row0 + lrow) * CDIM + lhalf);
    const uint4* gBh = (const uint4*)(bh + (size_t)(col0 + lrow) * CDIM + lhalf);
    const uint4* gBl = (const uint4*)(bl + (size_t)(col0 + lrow) * CDIM + lhalf);

    float acc[2][8][4];
    #pragma unroll
    for (int mc = 0; mc < 2; mc++)
        #pragma unroll
        for (int nc = 0; nc < 8; nc++)
            #pragma unroll
            for (int q = 0; q < 4; q++) acc[mc][nc][q] = 0.f;

    const int NT = CDIM / 32;
    for (int t = 0; t < NT; t++) {
        {
            uint4 va0 = gAh[t * 4], va1 = gAh[t * 4 + 1];
            uint4 wa0 = gAl[t * 4], wa1 = gAl[t * 4 + 1];
            uint4 vb0 = gBh[t * 4], vb1 = gBh[t * 4 + 1];
            uint4 wb0 = gBl[t * 4], wb1 = gBl[t * 4 + 1];
            uint2* p;
            p = (uint2*)(&Ah[lrow * S_LD + lhalf]);
            p[0] = make_uint2(va0.x, va0.y); p[1] = make_uint2(va0.z, va0.w);
            p[2] = make_uint2(va1.x, va1.y); p[3] = make_uint2(va1.z, va1.w);
            p = (uint2*)(&Al[lrow * S_LD + lhalf]);
            p[0] = make_uint2(wa0.x, wa0.y); p[1] = make_uint2(wa0.z, wa0.w);
            p[2] = make_uint2(wa1.x, wa1.y); p[3] = make_uint2(wa1.z, wa1.w);
            p = (uint2*)(&Bh[lrow * S_LD + lhalf]);
            p[0] = make_uint2(vb0.x, vb0.y); p[1] = make_uint2(vb0.z, vb0.w);
            p[2] = make_uint2(vb1.x, vb1.y); p[3] = make_uint2(vb1.z, vb1.w);
            p = (uint2*)(&Bl[lrow * S_LD + lhalf]);
            p[0] = make_uint2(wb0.x, wb0.y); p[1] = make_uint2(wb0.z, wb0.w);
            p[2] = make_uint2(wb1.x, wb1.y); p[3] = make_uint2(wb1.z, wb1.w);
        }
        __syncthreads();

        #pragma unroll
        for (int kk0 = 0; kk0 < 32; kk0 += 16) {
            uint32_t ahf[2][4], alf[2][4];
            #pragma unroll
            for (int mc = 0; mc < 2; mc++) {
                int base = (wm + mc * 16 + g) * S_LD + kk0 + 2 * tg;
                ahf[mc][0] = *(const uint32_t*)(&Ah[base]);
                ahf[mc][1] = *(const uint32_t*)(&Ah[base + 8 * S_LD]);
                ahf[mc][2] = *(const uint32_t*)(&Ah[base + 8]);
                ahf[mc][3] = *(const uint32_t*)(&Ah[base + 8 * S_LD + 8]);
                alf[mc][0] = *(const uint32_t*)(&Al[base]);
                alf[mc][1] = *(const uint32_t*)(&Al[base + 8 * S_LD]);
                alf[mc][2] = *(const uint32_t*)(&Al[base + 8]);
                alf[mc][3] = *(const uint32_t*)(&Al[base + 8 * S_LD + 8]);
            }
            #pragma unroll
            for (int nc = 0; nc < 8; nc++) {
                int bbase = (wn + nc * 8 + g) * S_LD + kk0 + 2 * tg;
                uint32_t bh0 = *(const uint32_t*)(&Bh[bbase]);
                uint32_t bh1 = *(const uint32_t*)(&Bh[bbase + 8]);
                uint32_t bl0 = *(const uint32_t*)(&Bl[bbase]);
                uint32_t bl1 = *(const uint32_t*)(&Bl[bbase + 8]);
                #pragma unroll
                for (int mc = 0; mc < 2; mc++) {
                    mma_bf16(acc[mc][nc], ahf[mc], bh0, bh1);
                    mma_bf16(acc[mc][nc], ahf[mc], bl0, bl1);
                    mma_bf16(acc[mc][nc], alf[mc], bh0, bh1);
                }
            }
        }
        __syncthreads();
    }

    #pragma unroll
    for (int mc = 0; mc < 2; mc++) {
        #pragma unroll
        for (int nc = 0; nc < 8; nc++) {
            int r = row0 + wm + mc * 16 + g;
            int c = col0 + wn + nc * 8 + 2 * tg;
            #pragma unroll
            for (int h = 0; h < 2; h++) {
                int rr = r + h * 8;
                float v0 = acc[mc][nc][h * 2 + 0];
                float v1 = acc[mc][nc][h * 2 + 1];
                if (HAS_BIAS) {
                    v0 = __fadd_rn(v0, bias[c]);
                    v1 = __fadd_rn(v1, bias[c + 1]);
                }
                *(float2*)(out + (size_t)rr * ldo + c) = make_float2(v0, v1);
                if (WRITE_SPLIT) {
                    __nv_bfloat16 h0 = __float2bfloat16_rn(v0);
                    __nv_bfloat16 h1 = __float2bfloat16_rn(v1);
                    __nv_bfloat16 l0 = __float2bfloat16_rn(v0 - __bfloat162float(h0));
                    __nv_bfloat16 l1 = __float2bfloat16_rn(v1 - __bfloat162float(h1));
                    __nv_bfloat16 ph[2] = {h0, h1};
                    __nv_bfloat16 pl[2] = {l0, l1};
                    *(uint32_t*)(out_hi + (size_t)rr * ldo + c) = *(uint32_t*)ph;
                    *(uint32_t*)(out_lo + (size_t)rr * ldo + c) = *(uint32_t*)pl;
                }
            }
        }
    }
}

// ============================================================================
// zero the ambiguous-row counter (graph-replayable reset)
// ============================================================================
__global__ void zero_amb() { g_amb_count = 0; }

// ============================================================================
// FUSED VQ: S-GEMM (split-bf16 3-term mma, validated inner loop) + top-2
// distance select. Each CTA: 128 obs rows x ALL 512 codes (4 code tiles).
// No S buffer. Unique winner iff d2 - d1 > VQ_BAND (== old single-candidate
// rule); else row goes to exact rescue.
// ============================================================================
#define TOP2_UPD(slot, dval, jidx) do {                                      \
    float _d = (dval); int _j = (jidx);                                      \
    if (_d < bd1[slot] || (_d == bd1[slot] && _j < bi1[slot])) {             \
        bd2[slot] = bd1[slot]; bd1[slot] = _d; bi1[slot] = _j;               \
    } else if (_d < bd2[slot]) bd2[slot] = _d;                               \
} while (0)

__global__ __launch_bounds__(256)
void vq_fused(const __nv_bfloat16* __restrict__ ah,
              const __nv_bfloat16* __restrict__ al,
              const __nv_bfloat16* __restrict__ bh,
              const __nv_bfloat16* __restrict__ bl,
              const float* __restrict__ cnorm,
              int* __restrict__ codes)
{
    __shared__ union {
        struct {
            __nv_bfloat16 Ah[128 * S_LD], Al[128 * S_LD];
            __nv_bfloat16 Bh[128 * S_LD], Bl[128 * S_LD];
        } t;
        struct { float d1[128 * 8]; int i1[128 * 8]; float d2[128 * 8]; } r;
    } sm;

    int tid  = threadIdx.x;
    int lane = tid & 31;
    int wid  = tid >> 5;
    int g    = lane >> 2;
    int tg   = lane & 3;
    int wm   = (wid >> 1) * 32;
    int wn   = (wid & 1) * 64;
    int row0 = blockIdx.x * 128;

    int lrow  = tid >> 1;
    int lhalf = (tid & 1) * 16;
    const uint4* gAh = (const uint4*)(ah + (size_t)(row0 + lrow) * CDIM + lhalf);
    const uint4* gAl = (const uint4*)(al + (size_t)(row0 + lrow) * CDIM + lhalf);

    float bd1[4], bd2[4];
    int   bi1[4];
    #pragma unroll
    for (int s = 0; s < 4; s++) { bd1[s] = 3.4e38f; bd2[s] = 3.4e38f; bi1[s] = 0x7fffffff; }

    for (int ct = 0; ct < 4; ct++) {
        int col0 = ct * 128;
        const uint4* gBh = (const uint4*)(bh + (size_t)(col0 + lrow) * CDIM + lhalf);
        const uint4* gBl = (const uint4*)(bl + (size_t)(col0 + lrow) * CDIM + lhalf);

        float acc[2][8][4];
        #pragma unroll
        for (int mc = 0; mc < 2; mc++)
            #pragma unroll
            for (int nc = 0; nc < 8; nc++)
                #pragma unroll
                for (int q = 0; q < 4; q++) acc[mc][nc][q] = 0.f;

        const int NT = CDIM / 32;
        for (int t = 0; t < NT; t++) {
            {
                uint4 va0 = gAh[t * 4], va1 = gAh[t * 4 + 1];
                uint4 wa0 = gAl[t * 4], wa1 = gAl[t * 4 + 1];
                uint4 vb0 = gBh[t * 4], vb1 = gBh[t * 4 + 1];
                uint4 wb0 = gBl[t * 4], wb1 = gBl[t * 4 + 1];
                uint2* p;
                p = (uint2*)(&sm.t.Ah[lrow * S_LD + lhalf]);
                p[0] = make_uint2(va0.x, va0.y); p[1] = make_uint2(va0.z, va0.w);
                p[2] = make_uint2(va1.x, va1.y); p[3] = make_uint2(va1.z, va1.w);
                p = (uint2*)(&sm.t.Al[lrow * S_LD + lhalf]);
                p[0] = make_uint2(wa0.x, wa0.y); p[1] = make_uint2(wa0.z, wa0.w);
                p[2] = make_uint2(wa1.x, wa1.y); p[3] = make_uint2(wa1.z, wa1.w);
                p = (uint2*)(&sm.t.Bh[lrow * S_LD + lhalf]);
                p[0] = make_uint2(vb0.x, vb0.y); p[1] = make_uint2(vb0.z, vb0.w);
                p[2] = make_uint2(vb1.x, vb1.y); p[3] = make_uint2(vb1.z, vb1.w);
                p = (uint2*)(&sm.t.Bl[lrow * S_LD + lhalf]);
                p[0] = make_uint2(wb0.x, wb0.y); p[1] = make_uint2(wb0.z, wb0.w);
                p[2] = make_uint2(wb1.x, wb1.y); p[3] = make_uint2(wb1.z, wb1.w);
            }
            __syncthreads();

            #pragma unroll
            for (int kk0 = 0; kk0 < 32; kk0 += 16) {
                uint32_t ahf[2][4], alf[2][4];
                #pragma unroll
                for (int mc = 0; mc < 2; mc++) {
                    int base = (wm + mc * 16 + g) * S_LD + kk0 + 2 * tg;
                    ahf[mc][0] = *(const uint32_t*)(&sm.t.Ah[base]);
                    ahf[mc][1] = *(const uint32_t*)(&sm.t.Ah[base + 8 * S_LD]);
                    ahf[mc][2] = *(const uint32_t*)(&sm.t.Ah[base + 8]);
                    ahf[mc][3] = *(const uint32_t*)(&sm.t.Ah[base + 8 * S_LD + 8]);
                    alf[mc][0] = *(const uint32_t*)(&sm.t.Al[base]);
                    alf[mc][1] = *(const uint32_t*)(&sm.t.Al[base + 8 * S_LD]);
                    alf[mc][2] = *(const uint32_t*)(&sm.t.Al[base + 8]);
                    alf[mc][3] = *(const uint32_t*)(&sm.t.Al[base + 8 * S_LD + 8]);
                }
                #pragma unroll
                for (int nc = 0; nc < 8; nc++) {
                    int bbase = (wn + nc * 8 + g) * S_LD + kk0 + 2 * tg;
                    uint32_t bh0 = *(const uint32_t*)(&sm.t.Bh[bbase]);
                    uint32_t bh1 = *(const uint32_t*)(&sm.t.Bh[bbase + 8]);
                    uint32_t bl0 = *(const uint32_t*)(&sm.t.Bl[bbase]);
                    uint32_t bl1 = *(const uint32_t*)(&sm.t.Bl[bbase + 8]);
                    #pragma unroll
                    for (int mc = 0; mc < 2; mc++) {
                        mma_bf16(acc[mc][nc], ahf[mc], bh0, bh1);
                        mma_bf16(acc[mc][nc], ahf[mc], bl0, bl1);
                        mma_bf16(acc[mc][nc], alf[mc], bh0, bh1);
                    }
                }
            }
            __syncthreads();
        }

        // top-2 update for this code tile (register-only)
        #pragma unroll
        for (int nc = 0; nc < 8; nc++) {
            int c = col0 + wn + nc * 8 + 2 * tg;
            float cn0 = cnorm[c], cn1 = cnorm[c + 1];
            #pragma unroll
            for (int mc = 0; mc < 2; mc++) {
                #pragma unroll
                for (int h = 0; h < 2; h++) {
                    int slot = mc * 2 + h;
                    float d0 = cn0 - 2.0f * acc[mc][nc][h * 2 + 0];
                    float d1 = cn1 - 2.0f * acc[mc][nc][h * 2 + 1];
                    TOP2_UPD(slot, d0, c);
                    TOP2_UPD(slot, d1, c + 1);
                }
            }
        }
    }

    // cross-thread reduction: 8 groups per row (wn-half x tg)
    int grp = (wid & 1) * 4 + tg;
    #pragma unroll
    for (int slot = 0; slot < 4; slot++) {
        int row = wm + (slot >> 1) * 16 + (slot & 1) * 8 + g;   // slot = mc*2+h
        sm.r.d1[row * 8 + grp] = bd1[slot];
        sm.r.i1[row * 8 + grp] = bi1[slot];
        sm.r.d2[row * 8 + grp] = bd2[slot];
    }
    __syncthreads();
    if (tid < 128) {
        float d1 = 3.4e38f, d2 = 3.4e38f;
        int i1 = 0x7fffffff;
        #pragma unroll
        for (int q = 0; q < 8; q++) {
            float gd1 = sm.r.d1[tid * 8 + q];
            int   gi1 = sm.r.i1[tid * 8 + q];
            float gd2 = sm.r.d2[tid * 8 + q];
            if (gd1 < d1 || (gd1 == d1 && gi1 < i1)) { d2 = d1; d1 = gd1; i1 = gi1; }
            else if (gd1 < d2) d2 = gd1;
            if (gd2 < d2) d2 = gd2;
        }
        int row = row0 + tid;
        if (d2 - d1 > VQ_BAND) {
            codes[row] = i1;
        } else {
            int slot = atomicAdd(&g_amb_count, 1);
            g_amb_rows[slot] = row;
        }
    }
}

// ============================================================================
// Rescue: one 256-thread block per ambiguous row (grid-stride).
// Recomputes the obs row EXACTLY (ascending-k fmaf + __fadd_rn bias, bitwise
// the reference gemm chain), A in double, then EXACT d2 over ALL 512 codes
// with the validated op order and first-index ties. Fully reference-exact.
// ============================================================================
__global__ __launch_bounds__(256)
void vq_rescue(const float* __restrict__ h2, const float* __restrict__ w3,
               const float* __restrict__ b3, const float* __restrict__ cb,
               const float* __restrict__ cnorm, int* __restrict__ codes)
{
    __shared__ float orow[512];
    __shared__ double dsum[256];
    __shared__ float bvs[256];
    __shared__ int   bis[256];

    int t = threadIdx.x;
    int cnt = g_amb_count;
    for (int idx = blockIdx.x; idx < cnt; idx += gridDim.x) {
        int row = g_amb_rows[idx];
        int b = row >> 4, s = row & 15;
        const float* h2r = h2 + (size_t)b * HDIM;
        const float* w3b = w3 + (size_t)s * CDIM;

        // exact obs row (cols t, t+256), ascending-k single-accumulator fmaf
        float a0 = 0.f, a1 = 0.f;
        for (int k = 0; k < HDIM; k++) {
            float hv = h2r[k];
            const float* wr = w3b + (size_t)k * CSDIM;
            a0 = fmaf(hv, wr[t], a0);
            a1 = fmaf(hv, wr[t + 256], a1);
        }
        float v0 = __fadd_rn(a0, b3[s * CDIM + t]);
        float v1 = __fadd_rn(a1, b3[s * CDIM + t + 256]);
        orow[t] = v0;
        orow[t + 256] = v1;
        dsum[t] = (double)v0 * v0 + (double)v1 * v1;
        __syncthreads();
        for (int o = 128; o > 0; o >>= 1) {
            if (t < o) dsum[t] += dsum[t + o];
            __syncthreads();
        }
        float A = (float)dsum[0];

        // exact d2 for ALL 512 codes (2 per thread), reference op order
        float bv = 3.4e38f; int bi = CDIM;
        #pragma unroll
        for (int e = 0; e < 2; e++) {
            int j = t + e * 256;
            const float* crow = cb + (size_t)j * CDIM;
            float acc = 0.f;
            #pragma unroll 8
            for (int k = 0; k < CDIM; k++)
                acc = fmaf(orow[k], crow[k], acc);
            float twob = __fmul_rn(2.0f, acc);
            float t2   = __fadd_rn(A, -twob);
            float d    = __fadd_rn(t2, cnorm[j]);
            if (d < bv || (d == bv && j < bi)) { bv = d; bi = j; }
        }
        bvs[t] = bv; bis[t] = bi;
        __syncthreads();
        for (int o = 128; o > 0; o >>= 1) {
            if (t < o) {
                float ov = bvs[t + o]; int oi = bis[t + o];
                if (ov < bvs[t] || (ov == bvs[t] && oi < bis[t])) {
                    bvs[t] = ov; bis[t] = oi;
                }
            }
            __syncthreads();
        }
        if (t == 0) codes[row] = bis[0];
        __syncthreads();
    }
}

// ============================================================================
// latent[row] = codebook[codes[row]]
// ============================================================================
__global__ void gather_latent_kernel(const int* __restrict__ codes,
                                     const float* __restrict__ cb,
                                     float* __restrict__ latent)
{
    int row  = blockIdx.x * 2 + (threadIdx.x >> 7);
    int lane = threadIdx.x & 127;
    int c = codes[row];
    const float4* src = (const float4*)(cb + (size_t)c * CDIM);
    float4* dst = (float4*)(latent + (size_t)row * CDIM);
    dst[lane] = src[lane];
}

// ============================================================================
// launch
// ============================================================================
extern "C" void kernel_launch(void* const* d_in, const int* in_sizes, int n_in,
                              void* d_out, int out_size)
{
    const float* x    = (const float*)d_in[0];
    const float* ew1  = (const float*)d_in[1];
    const float* eb1  = (const float*)d_in[2];
    const float* ew2  = (const float*)d_in[3];
    const float* eb2  = (const float*)d_in[4];
    const float* ew3  = (const float*)d_in[5];
    const float* eb3  = (const float*)d_in[6];
    const float* cb   = (const float*)d_in[7];
    const float* dw1  = (const float*)d_in[8];
    const float* db1  = (const float*)d_in[9];
    const float* dw2  = (const float*)d_in[10];
    const float* db2  = (const float*)d_in[11];

    float* out        = (float*)d_out;
    float* out_recon  = out;                                     // [8192, 784]
    float* out_obs    = out + (size_t)BROWS * DDIM;              // [131072, 512]
    float* out_latent = out_obs + (size_t)BROWS * CSDIM;         // [131072, 512]

    float *h1, *h2, *cn, *tbl; int *codes;
    __nv_bfloat16 *ohi, *olo, *chi, *clo, *hh, *hl, *w3h, *w3l;
    cudaGetSymbolAddress((void**)&h1, g_h1);
    cudaGetSymbolAddress((void**)&h2, g_h2);
    cudaGetSymbolAddress((void**)&cn, g_cnorm);
    cudaGetSymbolAddress((void**)&tbl, g_table);
    cudaGetSymbolAddress((void**)&ohi, g_obs_hi);
    cudaGetSymbolAddress((void**)&olo, g_obs_lo);
    cudaGetSymbolAddress((void**)&chi, g_cb_hi);
    cudaGetSymbolAddress((void**)&clo, g_cb_lo);
    cudaGetSymbolAddress((void**)&hh, g_h2h);
    cudaGetSymbolAddress((void**)&hl, g_h2l);
    cudaGetSymbolAddress((void**)&w3h, g_w3th);
    cudaGetSymbolAddress((void**)&w3l, g_w3tl);
    cudaGetSymbolAddress((void**)&codes, g_codes);

    // codebook- and weight-derived preprocessing
    zero_amb<<<1, 1>>>();
    cnorm_kernel<<<CDIM / 8, 256>>>(cb, cn);
    convert_split<<<(CDIM * CDIM / 8) / 256, 256>>>(cb, chi, clo, CDIM * CDIM / 8);
    w3t_split<<<dim3(CSDIM / 32, CDIM / 32), 256>>>(ew3, w3h, w3l);
    table_gemm<<<dim3(4, 4, SDIM), 256>>>(cb, dw1, tbl);

    // encoder (exact: enc1, enc2 feed both approx path and rescue)
    gemm_small<1,1><<<dim3(4, 64), 256>>>(x,  ew1, eb1, h1, HDIM, DDIM, HDIM);
    gemm_small<1,1><<<dim3(4, 64), 256>>>(h1, ew2, eb2, h2, HDIM, HDIM, HDIM);

    // enc3 approx on tensor cores: obs = h2 @ W3 + b3 (split-bf16 3-term)
    h2_split<<<(BROWS * 128 + 255) / 256, 256>>>(h2, hh, hl);
    mma3_gemm<1,1><<<dim3(CSDIM / 128, BROWS / 128), 256>>>(
        hh, hl, w3h, w3l, eb3, out_obs, CSDIM, ohi, olo);

    // fused VQ: S-GEMM + top-2 select (no S buffer), then exact rescue
    vq_fused<<<NROWS2 / 128, 256>>>(ohi, olo, chi, clo, cn, codes);
    vq_rescue<<<2048, 256>>>(h2, ew3, eb3, cb, cn, codes);
    gather_latent_kernel<<<NROWS2 / 2, 256>>>(codes, cb, out_latent);

    // decoder
    dec1_gather<<<BROWS / 2, 256>>>(codes, tbl, db1, h1);
    gemm_small<0,1><<<dim3(7, 64), 256>>>(h1, dw2, db2, out_recon, DDIM, HDIM, DDIM);
}